// round 4
// baseline (speedup 1.0000x reference)
#include <cuda_runtime.h>
#include <cstddef>

#define BB  64
#define NNODE 1000
#define EE  64
#define OO  16
#define HH  128
#define FUT 12
#define G4  512   // 4*H

// ---------------- device scratch (static, no allocations) ----------------
__device__ float g_nm[(size_t)BB * NNODE * OO];            // 4 MB  : node_mean
__device__ float g_genc[(size_t)BB * NNODE * G4];          // 131 MB: enc@W_e^T + b_ih0 + b_hh0

// ---------------- kernel 1: node_mean = mean(mean, axis=FUT) -------------
__global__ void nm_kernel(const float* __restrict__ mean) {
    int idx = blockIdx.x * blockDim.x + threadIdx.x;      // over B*N*O
    if (idx >= BB * NNODE * OO) return;
    int o = idx & (OO - 1);
    int n = (idx >> 4) % NNODE;
    int b = idx / (NNODE * OO);
    float s = 0.f;
#pragma unroll
    for (int f = 0; f < FUT; f++)
        s += mean[(((size_t)b * FUT + f) * NNODE + n) * OO + o];
    g_nm[idx] = s * (1.0f / FUT);
}

// ---------------- kernel 2: G_enc precompute ------------------------------
// G_enc[r][g] = sum_e W_ih_l0[g][e] * enc[r][e] + b_ih_l0[g] + b_hh_l0[g]
__global__ __launch_bounds__(512) void genc_kernel(
    const float* __restrict__ enc,
    const float* __restrict__ Wih0,
    const float* __restrict__ bih0,
    const float* __restrict__ bhh0)
{
    int g = threadIdx.x;                                   // gate 0..511
    float w[64];
#pragma unroll
    for (int e = 0; e < 64; e++) w[e] = Wih0[g * 80 + e];
    float bias = bih0[g] + bhh0[g];

    __shared__ __align__(16) float4 xs[16];                // one enc row (64 f)
    int total = BB * NNODE;
    int per = (total + gridDim.x - 1) / gridDim.x;
    int r0 = blockIdx.x * per;
    int r1 = min(r0 + per, total);
    for (int r = r0; r < r1; r++) {
        __syncthreads();
        if (g < 16) xs[g] = ((const float4*)(enc + (size_t)r * 64))[g];
        __syncthreads();
        float acc = bias;
#pragma unroll
        for (int e4 = 0; e4 < 16; e4++) {
            float4 x = xs[e4];
            acc += w[e4*4+0]*x.x + w[e4*4+1]*x.y + w[e4*4+2]*x.z + w[e4*4+3]*x.w;
        }
        g_genc[(size_t)r * G4 + g] = acc;
    }
}

// ---------------- kernel 3: sequential recurrence --------------------------
__device__ __forceinline__ float sigm(float x) {
    return 1.0f / (1.0f + expf(-x));
}

__global__ __launch_bounds__(256, 1) void rec_kernel(
    const float* __restrict__ s0,    // (1,16)
    const float* __restrict__ h0,    // (2,16)
    const float* __restrict__ c0,    // (2,128)
    const float* __restrict__ Wih0,  // (512,80)
    const float* __restrict__ Whh0,  // (512,16)
    const float* __restrict__ Whr0,  // (16,128)
    const float* __restrict__ Wih1,  // (512,16)
    const float* __restrict__ Whh1,  // (512,16)
    const float* __restrict__ bih1,  // (512)
    const float* __restrict__ bhh1,  // (512)
    const float* __restrict__ Whr1,  // (16,128)
    float* __restrict__ out)         // (B,FUT,N,O)
{
    const int b   = blockIdx.x;      // one batch element per CTA
    const int tid = threadIdx.x;
    const int k   = tid & 127;       // hidden unit id within layer
    const bool isL0 = tid < 128;     // warps 0-3: layer0, warps 4-7: layer1

    __shared__ __align__(16) float s_last[16];
    __shared__ __align__(16) float s_h1[16];
    __shared__ __align__(16) float s_h2[16];
    __shared__ __align__(16) float s_nm[16];
    __shared__ __align__(16) float s_hf[128];

    // register-resident weights: wa,wb are the two K=16 dot operands for the
    // 4 gate rows this thread owns (layer 0 or layer 1 depending on tid).
    float wa[4][16], wb[4][16], bias[4];
    float wpr[16];                   // projection weights (16-elem segment)
    float c_reg;                     // c1[k] (L0 threads) or c2[k] (L1 threads)

    {
        int o = k >> 3, gl = k & 7;
        if (isL0) {
#pragma unroll
            for (int q = 0; q < 4; q++) {
                int g = q * 128 + k;
#pragma unroll
                for (int j = 0; j < 16; j++) {
                    wa[q][j] = Wih0[g * 80 + 64 + j];   // multiplies loop=last+nm
                    wb[q][j] = Whh0[g * 16 + j];        // multiplies h1_prev
                }
                bias[q] = 0.f;                          // bias folded into G_enc
            }
            c_reg = c0[k];
#pragma unroll
            for (int j = 0; j < 16; j++) wpr[j] = Whr0[o * 128 + gl * 16 + j];
        } else {
#pragma unroll
            for (int q = 0; q < 4; q++) {
                int g = q * 128 + k;
#pragma unroll
                for (int j = 0; j < 16; j++) {
                    wa[q][j] = Wih1[g * 16 + j];        // multiplies h1_new
                    wb[q][j] = Whh1[g * 16 + j];        // multiplies h2_prev
                }
                bias[q] = bih1[g] + bhh1[g];
            }
            c_reg = c0[128 + k];
#pragma unroll
            for (int j = 0; j < 16; j++) wpr[j] = Whr1[o * 128 + gl * 16 + j];
        }
    }

    if (tid < 16) {
        s_last[tid] = s0[tid];         // last0 = s[0]
        s_h1[tid]   = h0[tid];         // h1_0  = h_0[0]
        s_h2[tid]   = h0[16 + tid];    // h2_0  = h_0[1]
    }

    // node-ahead prefetch state
    float genc_c[4], genc_n[4], gnm[4];
    float nm_pref = 0.f;
    if (isL0) {
        size_t base = ((size_t)b * NNODE + 0) * G4 + k;
#pragma unroll
        for (int q = 0; q < 4; q++) genc_n[q] = g_genc[base + q * 128];
    } else if (k < 16) {
        nm_pref = g_nm[(size_t)b * NNODE * OO + k];
    }

    int n = 0, f = 0;
    for (int t = 0; t < NNODE * FUT; t++) {
        if (f == 0) {
            // ---- node boundary: publish nm, fold gnm, prefetch node n+1 ----
            if (!isL0 && k < 16) s_nm[k] = nm_pref;
            __syncthreads();
            if (isL0) {
#pragma unroll
                for (int q = 0; q < 4; q++) genc_c[q] = genc_n[q];
#pragma unroll
                for (int q = 0; q < 4; q++) {
                    float a = 0.f;
#pragma unroll
                    for (int j = 0; j < 16; j++) a += wa[q][j] * s_nm[j];
                    gnm[q] = a;       // W_loop . nm  (constant for this node)
                }
                int nn = (n + 1 < NNODE) ? n + 1 : n;
                size_t base = ((size_t)b * NNODE + nn) * G4 + k;
#pragma unroll
                for (int q = 0; q < 4; q++) genc_n[q] = g_genc[base + q * 128];
            } else if (k < 16) {
                int nn = (n + 1 < NNODE) ? n + 1 : n;
                nm_pref = g_nm[((size_t)b * NNODE + nn) * OO + k];
            }
        }

        float acc0, acc1, acc2, acc3;
        if (isL0) {
            // ---- P1: layer0 gates + activation + c1 update (exchange-free) ----
            acc0 = genc_c[0] + gnm[0];
            acc1 = genc_c[1] + gnm[1];
            acc2 = genc_c[2] + gnm[2];
            acc3 = genc_c[3] + gnm[3];
            const float4* l4 = (const float4*)s_last;
            const float4* h4 = (const float4*)s_h1;
#pragma unroll
            for (int j4 = 0; j4 < 4; j4++) {
                float4 xl = l4[j4];
                float4 xh = h4[j4];
                float xlv[4] = {xl.x, xl.y, xl.z, xl.w};
                float xhv[4] = {xh.x, xh.y, xh.z, xh.w};
#pragma unroll
                for (int jj = 0; jj < 4; jj++) {
                    int j = j4 * 4 + jj;
                    acc0 += wa[0][j] * xlv[jj] + wb[0][j] * xhv[jj];
                    acc1 += wa[1][j] * xlv[jj] + wb[1][j] * xhv[jj];
                    acc2 += wa[2][j] * xlv[jj] + wb[2][j] * xhv[jj];
                    acc3 += wa[3][j] * xlv[jj] + wb[3][j] * xhv[jj];
                }
            }
            float ig = sigm(acc0), fg = sigm(acc1);
            float gg = tanhf(acc2), og = sigm(acc3);
            c_reg = fg * c_reg + ig * gg;
            s_hf[k] = og * tanhf(c_reg);
        } else {
            // ---- layer1 partial: b1 + W_hh1 . h2_prev (available now) ----
            acc0 = bias[0]; acc1 = bias[1]; acc2 = bias[2]; acc3 = bias[3];
            const float4* h24 = (const float4*)s_h2;
#pragma unroll
            for (int j4 = 0; j4 < 4; j4++) {
                float4 x = h24[j4];
                float xv[4] = {x.x, x.y, x.z, x.w};
#pragma unroll
                for (int jj = 0; jj < 4; jj++) {
                    int j = j4 * 4 + jj;
                    acc0 += wb[0][j] * xv[jj];
                    acc1 += wb[1][j] * xv[jj];
                    acc2 += wb[2][j] * xv[jj];
                    acc3 += wb[3][j] * xv[jj];
                }
            }
        }
        __syncthreads();   // bar1: hf(layer0) visible

        if (isL0) {
            // ---- P2: projection h1 = W_hr0 @ hf (8 lanes per output) ----
            int gl = k & 7;
            const float4* hf4 = (const float4*)(s_hf + gl * 16);
            float p = 0.f;
#pragma unroll
            for (int j4 = 0; j4 < 4; j4++) {
                float4 x = hf4[j4];
                p += wpr[j4*4+0]*x.x + wpr[j4*4+1]*x.y + wpr[j4*4+2]*x.z + wpr[j4*4+3]*x.w;
            }
            p += __shfl_xor_sync(0xffffffffu, p, 4);
            p += __shfl_xor_sync(0xffffffffu, p, 2);
            p += __shfl_xor_sync(0xffffffffu, p, 1);
            if (gl == 0) s_h1[k >> 3] = p;
        }
        __syncthreads();   // bar2: h1 visible, hf free

        if (!isL0) {
            // ---- P3: layer1 gates finish + activation + c2 update ----
            const float4* h14 = (const float4*)s_h1;
#pragma unroll
            for (int j4 = 0; j4 < 4; j4++) {
                float4 x = h14[j4];
                float xv[4] = {x.x, x.y, x.z, x.w};
#pragma unroll
                for (int jj = 0; jj < 4; jj++) {
                    int j = j4 * 4 + jj;
                    acc0 += wa[0][j] * xv[jj];
                    acc1 += wa[1][j] * xv[jj];
                    acc2 += wa[2][j] * xv[jj];
                    acc3 += wa[3][j] * xv[jj];
                }
            }
            float ig = sigm(acc0), fg = sigm(acc1);
            float gg = tanhf(acc2), og = sigm(acc3);
            c_reg = fg * c_reg + ig * gg;
            s_hf[k] = og * tanhf(c_reg);
        }
        __syncthreads();   // bar3: hf(layer1) visible

        if (!isL0) {
            // ---- P4: projection h2 = W_hr1 @ hf2, publish state + output ----
            int gl = k & 7;
            const float4* hf4 = (const float4*)(s_hf + gl * 16);
            float p = 0.f;
#pragma unroll
            for (int j4 = 0; j4 < 4; j4++) {
                float4 x = hf4[j4];
                p += wpr[j4*4+0]*x.x + wpr[j4*4+1]*x.y + wpr[j4*4+2]*x.z + wpr[j4*4+3]*x.w;
            }
            p += __shfl_xor_sync(0xffffffffu, p, 4);
            p += __shfl_xor_sync(0xffffffffu, p, 2);
            p += __shfl_xor_sync(0xffffffffu, p, 1);
            if (gl == 0) {
                int o = k >> 3;
                s_h2[o]   = p;
                s_last[o] = p;    // carry: last = h2
                out[(((size_t)b * FUT + f) * NNODE + n) * OO + o] = p + s_nm[o];
            }
        }
        __syncthreads();   // bar4: state visible for next step

        if (++f == FUT) { f = 0; ++n; }
    }
}

// ---------------- launch ----------------------------------------------------
extern "C" void kernel_launch(void* const* d_in, const int* in_sizes, int n_in,
                              void* d_out, int out_size)
{
    const float* enc  = (const float*)d_in[0];   // (64,1,1000,64)
    const float* mean = (const float*)d_in[1];   // (64,12,1000,16)
    const float* s    = (const float*)d_in[2];   // (1,16)
    const float* h0   = (const float*)d_in[3];   // (2,16)
    const float* c0   = (const float*)d_in[4];   // (2,128)
    const float* Wih0 = (const float*)d_in[5];   // (512,80)
    const float* Whh0 = (const float*)d_in[6];   // (512,16)
    const float* bih0 = (const float*)d_in[7];   // (512)
    const float* bhh0 = (const float*)d_in[8];   // (512)
    const float* Whr0 = (const float*)d_in[9];   // (16,128)
    const float* Wih1 = (const float*)d_in[10];  // (512,16)
    const float* Whh1 = (const float*)d_in[11];  // (512,16)
    const float* bih1 = (const float*)d_in[12];  // (512)
    const float* bhh1 = (const float*)d_in[13];  // (512)
    const float* Whr1 = (const float*)d_in[14];  // (16,128)
    float* out = (float*)d_out;                  // (64,12,1000,16) fp32

    nm_kernel<<<(BB * NNODE * OO + 255) / 256, 256>>>(mean);
    genc_kernel<<<148, 512>>>(enc, Wih0, bih0, bhh0);
    rec_kernel<<<BB, 256>>>(s, h0, c0, Wih0, Whh0, Whr0,
                            Wih1, Whh1, bih1, bhh1, Whr1, out);
}

// round 5
// speedup vs baseline: 1.3434x; 1.3434x over previous
#include <cuda_runtime.h>
#include <cstddef>

#define BB  64
#define NNODE 1000
#define EE  64
#define OO  16
#define HH  128
#define FUT 12
#define G4  512   // 4*H

typedef unsigned long long ull;

// ---------------- device scratch (static, no allocations) ----------------
__device__ float g_nm[(size_t)BB * NNODE * OO];            // 4 MB  : node_mean
__device__ float g_genc[(size_t)BB * NNODE * G4];          // 131 MB: enc@W_e^T + b_ih0 + b_hh0

// ---------------- packed f32x2 helpers ------------------------------------
__device__ __forceinline__ void ffma2(ull& acc, ull a, ull b) {
    asm("fma.rn.f32x2 %0, %1, %2, %0;" : "+l"(acc) : "l"(a), "l"(b));
}
__device__ __forceinline__ ull pk(float lo, float hi) {
    ull r;
    asm("mov.b64 %0, {%1, %2};" : "=l"(r) : "f"(lo), "f"(hi));
    return r;
}
__device__ __forceinline__ float hsum(ull v) {
    float lo, hi;
    asm("mov.b64 {%0, %1}, %2;" : "=f"(lo), "=f"(hi) : "l"(v));
    return lo + hi;
}

// fast activations: EX2/RCP based (~1e-6 rel err, no branches)
__device__ __forceinline__ float sigm(float x) {
    return __fdividef(1.0f, 1.0f + __expf(-x));
}
__device__ __forceinline__ float tanhfast(float x) {
    return 1.0f - __fdividef(2.0f, 1.0f + __expf(2.0f * x));
}

#define BAR_L0() asm volatile("bar.sync 1, 128;" ::: "memory")
#define BAR_L1() asm volatile("bar.sync 2, 128;" ::: "memory")

// ---------------- kernel 1: node_mean = mean(mean, axis=FUT) -------------
__global__ void nm_kernel(const float* __restrict__ mean) {
    int idx = blockIdx.x * blockDim.x + threadIdx.x;      // over B*N*4 float4s
    if (idx >= BB * NNODE * 4) return;
    int q = idx & 3;
    int n = (idx >> 2) % NNODE;
    int b = idx / (NNODE * 4);
    float4 s = make_float4(0.f, 0.f, 0.f, 0.f);
    const float4* m4 = (const float4*)mean;
#pragma unroll
    for (int f = 0; f < FUT; f++) {
        float4 v = m4[(((size_t)b * FUT + f) * NNODE + n) * 4 + q];
        s.x += v.x; s.y += v.y; s.z += v.z; s.w += v.w;
    }
    const float inv = 1.0f / FUT;
    s.x *= inv; s.y *= inv; s.z *= inv; s.w *= inv;
    ((float4*)g_nm)[idx] = s;
}

// ---------------- kernel 2: G_enc precompute ------------------------------
__global__ __launch_bounds__(512) void genc_kernel(
    const float* __restrict__ enc,
    const float* __restrict__ Wih0,
    const float* __restrict__ bih0,
    const float* __restrict__ bhh0)
{
    int g = threadIdx.x;                                   // gate 0..511
    float w[64];
#pragma unroll
    for (int e = 0; e < 64; e++) w[e] = Wih0[g * 80 + e];
    float bias = bih0[g] + bhh0[g];

    __shared__ __align__(16) float4 xs[16];                // one enc row (64 f)
    int total = BB * NNODE;
    int per = (total + gridDim.x - 1) / gridDim.x;
    int r0 = blockIdx.x * per;
    int r1 = min(r0 + per, total);
    for (int r = r0; r < r1; r++) {
        __syncthreads();
        if (g < 16) xs[g] = ((const float4*)(enc + (size_t)r * 64))[g];
        __syncthreads();
        float acc = bias;
#pragma unroll
        for (int e4 = 0; e4 < 16; e4++) {
            float4 x = xs[e4];
            acc += w[e4*4+0]*x.x + w[e4*4+1]*x.y + w[e4*4+2]*x.z + w[e4*4+3]*x.w;
        }
        g_genc[(size_t)r * G4 + g] = acc;
    }
}

// ---------------- kernel 3: sequential recurrence --------------------------
__global__ __launch_bounds__(256, 1) void rec_kernel(
    const float* __restrict__ s0,    // (1,16)
    const float* __restrict__ h0,    // (2,16)
    const float* __restrict__ c0,    // (2,128)
    const float* __restrict__ Wih0,  // (512,80)
    const float* __restrict__ Whh0,  // (512,16)
    const float* __restrict__ Whr0,  // (16,128)
    const float* __restrict__ Wih1,  // (512,16)
    const float* __restrict__ Whh1,  // (512,16)
    const float* __restrict__ bih1,  // (512)
    const float* __restrict__ bhh1,  // (512)
    const float* __restrict__ Whr1,  // (16,128)
    float* __restrict__ out)         // (B,FUT,N,O)
{
    const int b   = blockIdx.x;      // one batch element per CTA
    const int tid = threadIdx.x;
    const int k   = tid & 127;       // hidden unit id within layer
    const bool isL0 = tid < 128;     // warps 0-3: layer0, warps 4-7: layer1
    const int gl = k & 7;
    const int oo = k >> 3;

    // s_x0: [0:16) = last (= h2 carry), [16:32) = h1   (contiguous for L0 dot)
    __shared__ __align__(16) float s_x0[32];
    __shared__ __align__(16) float s_h2[16];
    __shared__ __align__(16) float s_nm[16];
    __shared__ __align__(16) float s_hf[128];

    // packed weights: per gate q, 16 ull (= 32 floats)
    //  L0: [0:8) = W_ih0 loop part (mult. last & nm), [8:16) = W_hh0 (mult. h1)
    //  L1: [0:8) = W_ih1 (mult. h1_new),              [8:16) = W_hh1 (mult. h2_prev)
    ull w2[4][16];
    ull wpr2[8];
    float bias[4];
    float c_reg;

    if (isL0) {
#pragma unroll
        for (int q = 0; q < 4; q++) {
            int g = q * 128 + k;
#pragma unroll
            for (int j = 0; j < 8; j++) {
                w2[q][j]     = pk(Wih0[g * 80 + 64 + 2*j], Wih0[g * 80 + 64 + 2*j + 1]);
                w2[q][8 + j] = pk(Whh0[g * 16 + 2*j],      Whh0[g * 16 + 2*j + 1]);
            }
            bias[q] = 0.f;                          // folded into G_enc
        }
        c_reg = c0[k];
#pragma unroll
        for (int j = 0; j < 8; j++)
            wpr2[j] = pk(Whr0[oo * 128 + gl * 16 + 2*j], Whr0[oo * 128 + gl * 16 + 2*j + 1]);
    } else {
#pragma unroll
        for (int q = 0; q < 4; q++) {
            int g = q * 128 + k;
#pragma unroll
            for (int j = 0; j < 8; j++) {
                w2[q][j]     = pk(Wih1[g * 16 + 2*j], Wih1[g * 16 + 2*j + 1]);
                w2[q][8 + j] = pk(Whh1[g * 16 + 2*j], Whh1[g * 16 + 2*j + 1]);
            }
            bias[q] = bih1[g] + bhh1[g];
        }
        c_reg = c0[128 + k];
#pragma unroll
        for (int j = 0; j < 8; j++)
            wpr2[j] = pk(Whr1[oo * 128 + gl * 16 + 2*j], Whr1[oo * 128 + gl * 16 + 2*j + 1]);
    }

    if (tid < 16) {
        s_x0[tid]      = s0[tid];      // last0 = s[0]
        s_x0[16 + tid] = h0[tid];      // h1_0  = h_0[0]
        s_h2[tid]      = h0[16 + tid]; // h2_0  = h_0[1]
    }

    // node-ahead prefetch state
    float genc_c[4], genc_n[4], gnm[4];
    float nm_pref = 0.f;
    if (isL0) {
        size_t base = ((size_t)b * NNODE + 0) * G4 + k;
#pragma unroll
        for (int q = 0; q < 4; q++) genc_n[q] = g_genc[base + q * 128];
    } else if (k < 16) {
        nm_pref = g_nm[(size_t)b * NNODE * OO + k];
    }

    int n = 0, f = 0;
    for (int t = 0; t < NNODE * FUT; t++) {
        if (f == 0) {
            // ---- node boundary: publish nm, fold gnm, prefetch node n+1 ----
            if (!isL0 && k < 16) s_nm[k] = nm_pref;
            __syncthreads();
            if (isL0) {
#pragma unroll
                for (int q = 0; q < 4; q++) genc_c[q] = genc_n[q];
                ull a[4];
#pragma unroll
                for (int q = 0; q < 4; q++) a[q] = pk(0.f, 0.f);
                const ulonglong2* nm4 = (const ulonglong2*)s_nm;
#pragma unroll
                for (int i = 0; i < 4; i++) {
                    ulonglong2 xx = nm4[i];
#pragma unroll
                    for (int q = 0; q < 4; q++) {
                        ffma2(a[q], w2[q][2*i],     xx.x);
                        ffma2(a[q], w2[q][2*i + 1], xx.y);
                    }
                }
#pragma unroll
                for (int q = 0; q < 4; q++) gnm[q] = hsum(a[q]);
                int nn = (n + 1 < NNODE) ? n + 1 : n;
                size_t base = ((size_t)b * NNODE + nn) * G4 + k;
#pragma unroll
                for (int q = 0; q < 4; q++) genc_n[q] = g_genc[base + q * 128];
            } else if (k < 16) {
                int nn = (n + 1 < NNODE) ? n + 1 : n;
                nm_pref = g_nm[((size_t)b * NNODE + nn) * OO + k];
            }
        }

        ull acc[4];
        if (isL0) {
            // ---- P1: layer0 gates over contiguous x = [last | h1] ----
#pragma unroll
            for (int q = 0; q < 4; q++) acc[q] = pk(genc_c[q] + gnm[q], 0.f);
            const ulonglong2* x4 = (const ulonglong2*)s_x0;     // 8 x 16B
#pragma unroll
            for (int i = 0; i < 8; i++) {
                ulonglong2 xx = x4[i];
#pragma unroll
                for (int q = 0; q < 4; q++) {
                    ffma2(acc[q], w2[q][2*i],     xx.x);
                    ffma2(acc[q], w2[q][2*i + 1], xx.y);
                }
            }
            float ig = sigm(hsum(acc[0]));
            float fg = sigm(hsum(acc[1]));
            float gg = tanhfast(hsum(acc[2]));
            float og = sigm(hsum(acc[3]));
            c_reg = fg * c_reg + ig * gg;
            s_hf[k] = og * tanhfast(c_reg);
            BAR_L0();   // hf(L0) visible within L0 group

            // ---- P2: projection h1 = W_hr0 @ hf ----
            const ulonglong2* hf4 = (const ulonglong2*)(s_hf + gl * 16);
            ull pa = pk(0.f, 0.f);
#pragma unroll
            for (int i = 0; i < 4; i++) {
                ulonglong2 xx = hf4[i];
                ffma2(pa, wpr2[2*i],     xx.x);
                ffma2(pa, wpr2[2*i + 1], xx.y);
            }
            float p = hsum(pa);
            p += __shfl_xor_sync(0xffffffffu, p, 4);
            p += __shfl_xor_sync(0xffffffffu, p, 2);
            p += __shfl_xor_sync(0xffffffffu, p, 1);
            if (gl == 0) s_x0[16 + oo] = p;
        } else {
            // ---- layer1 partial: b1 + W_hh1 . h2_prev ----
#pragma unroll
            for (int q = 0; q < 4; q++) acc[q] = pk(bias[q], 0.f);
            const ulonglong2* h24 = (const ulonglong2*)s_h2;
#pragma unroll
            for (int i = 0; i < 4; i++) {
                ulonglong2 xx = h24[i];
#pragma unroll
                for (int q = 0; q < 4; q++) {
                    ffma2(acc[q], w2[q][8 + 2*i], xx.x);
                    ffma2(acc[q], w2[q][9 + 2*i], xx.y);
                }
            }
        }
        __syncthreads();   // bar2: h1 visible to L1

        if (!isL0) {
            // ---- P3: layer1 gates finish + activation + c2 update ----
            const ulonglong2* h14 = (const ulonglong2*)(s_x0 + 16);
#pragma unroll
            for (int i = 0; i < 4; i++) {
                ulonglong2 xx = h14[i];
#pragma unroll
                for (int q = 0; q < 4; q++) {
                    ffma2(acc[q], w2[q][2*i],     xx.x);
                    ffma2(acc[q], w2[q][2*i + 1], xx.y);
                }
            }
            float ig = sigm(hsum(acc[0]));
            float fg = sigm(hsum(acc[1]));
            float gg = tanhfast(hsum(acc[2]));
            float og = sigm(hsum(acc[3]));
            c_reg = fg * c_reg + ig * gg;
            s_hf[k] = og * tanhfast(c_reg);
            BAR_L1();   // hf(L1) visible within L1 group

            // ---- P4: projection h2 = W_hr1 @ hf2, publish state + output ----
            const ulonglong2* hf4 = (const ulonglong2*)(s_hf + gl * 16);
            ull pa = pk(0.f, 0.f);
#pragma unroll
            for (int i = 0; i < 4; i++) {
                ulonglong2 xx = hf4[i];
                ffma2(pa, wpr2[2*i],     xx.x);
                ffma2(pa, wpr2[2*i + 1], xx.y);
            }
            float p = hsum(pa);
            p += __shfl_xor_sync(0xffffffffu, p, 4);
            p += __shfl_xor_sync(0xffffffffu, p, 2);
            p += __shfl_xor_sync(0xffffffffu, p, 1);
            if (gl == 0) {
                s_h2[oo] = p;
                s_x0[oo] = p;    // carry: last = h2
                out[(((size_t)b * FUT + f) * NNODE + n) * OO + oo] = p + s_nm[oo];
            }
        }
        __syncthreads();   // bar4: state visible for next step

        if (++f == FUT) { f = 0; ++n; }
    }
}

// ---------------- launch ----------------------------------------------------
extern "C" void kernel_launch(void* const* d_in, const int* in_sizes, int n_in,
                              void* d_out, int out_size)
{
    const float* enc  = (const float*)d_in[0];   // (64,1,1000,64)
    const float* mean = (const float*)d_in[1];   // (64,12,1000,16)
    const float* s    = (const float*)d_in[2];   // (1,16)
    const float* h0   = (const float*)d_in[3];   // (2,16)
    const float* c0   = (const float*)d_in[4];   // (2,128)
    const float* Wih0 = (const float*)d_in[5];   // (512,80)
    const float* Whh0 = (const float*)d_in[6];   // (512,16)
    const float* bih0 = (const float*)d_in[7];   // (512)
    const float* bhh0 = (const float*)d_in[8];   // (512)
    const float* Whr0 = (const float*)d_in[9];   // (16,128)
    const float* Wih1 = (const float*)d_in[10];  // (512,16)
    const float* Whh1 = (const float*)d_in[11];  // (512,16)
    const float* bih1 = (const float*)d_in[12];  // (512)
    const float* bhh1 = (const float*)d_in[13];  // (512)
    const float* Whr1 = (const float*)d_in[14];  // (16,128)
    float* out = (float*)d_out;                  // (64,12,1000,16) fp32

    nm_kernel<<<(BB * NNODE * 4 + 255) / 256, 256>>>(mean);
    genc_kernel<<<148, 512>>>(enc, Wih0, bih0, bhh0);
    rec_kernel<<<BB, 256>>>(s, h0, c0, Wih0, Whh0, Whr0,
                            Wih1, Whh1, bih1, bhh1, Whr1, out);
}

// round 6
// speedup vs baseline: 1.5908x; 1.1842x over previous
#include <cuda_runtime.h>
#include <cstddef>

#define BB  64
#define NNODE 1000
#define EE  64
#define OO  16
#define HH  128
#define FUT 12
#define G4  512   // 4*H
#define TOT (NNODE * FUT)

typedef unsigned long long ull;

// ---------------- device scratch (static, no allocations) ----------------
__device__ float g_nm[(size_t)BB * NNODE * OO];            // 4 MB  : node_mean
__device__ float g_genc[(size_t)BB * NNODE * G4];          // 131 MB: enc@W_e^T + b_ih0 + b_hh0

// ---------------- packed f32x2 helpers ------------------------------------
__device__ __forceinline__ void ffma2(ull& acc, ull a, ull b) {
    asm("fma.rn.f32x2 %0, %1, %2, %0;" : "+l"(acc) : "l"(a), "l"(b));
}
__device__ __forceinline__ ull pk(float lo, float hi) {
    ull r;
    asm("mov.b64 %0, {%1, %2};" : "=l"(r) : "f"(lo), "f"(hi));
    return r;
}
__device__ __forceinline__ float hsum(ull v) {
    float lo, hi;
    asm("mov.b64 {%0, %1}, %2;" : "=f"(lo), "=f"(hi) : "l"(v));
    return lo + hi;
}

// fast activations: EX2/RCP based (~1e-6 rel err, no branches)
__device__ __forceinline__ float sigm(float x) {
    return __fdividef(1.0f, 1.0f + __expf(-x));
}
__device__ __forceinline__ float tanhfast(float x) {
    return 1.0f - __fdividef(2.0f, 1.0f + __expf(2.0f * x));
}

// named barriers: 1/2 intra-group (128), 3/4 producer->consumer (256 total)
#define BAR_L0()        asm volatile("bar.sync 1, 128;"   ::: "memory")
#define BAR_L1()        asm volatile("bar.sync 2, 128;"   ::: "memory")
#define BAR_H2_SYNC()   asm volatile("bar.sync 3, 256;"   ::: "memory")
#define BAR_H2_ARRIVE() asm volatile("bar.arrive 3, 256;" ::: "memory")
#define BAR_H1_SYNC()   asm volatile("bar.sync 4, 256;"   ::: "memory")
#define BAR_H1_ARRIVE() asm volatile("bar.arrive 4, 256;" ::: "memory")

// ---------------- kernel 1: node_mean = mean(mean, axis=FUT) -------------
__global__ void nm_kernel(const float* __restrict__ mean) {
    int idx = blockIdx.x * blockDim.x + threadIdx.x;      // over B*N*4 float4s
    if (idx >= BB * NNODE * 4) return;
    int q = idx & 3;
    int n = (idx >> 2) % NNODE;
    int b = idx / (NNODE * 4);
    float4 s = make_float4(0.f, 0.f, 0.f, 0.f);
    const float4* m4 = (const float4*)mean;
#pragma unroll
    for (int f = 0; f < FUT; f++) {
        float4 v = m4[(((size_t)b * FUT + f) * NNODE + n) * 4 + q];
        s.x += v.x; s.y += v.y; s.z += v.z; s.w += v.w;
    }
    const float inv = 1.0f / FUT;
    s.x *= inv; s.y *= inv; s.z *= inv; s.w *= inv;
    ((float4*)g_nm)[idx] = s;
}

// ---------------- kernel 2: G_enc precompute ------------------------------
__global__ __launch_bounds__(512) void genc_kernel(
    const float* __restrict__ enc,
    const float* __restrict__ Wih0,
    const float* __restrict__ bih0,
    const float* __restrict__ bhh0)
{
    int g = threadIdx.x;                                   // gate 0..511
    float w[64];
#pragma unroll
    for (int e = 0; e < 64; e++) w[e] = Wih0[g * 80 + e];
    float bias = bih0[g] + bhh0[g];

    __shared__ __align__(16) float4 xs[16];                // one enc row (64 f)
    int total = BB * NNODE;
    int per = (total + gridDim.x - 1) / gridDim.x;
    int r0 = blockIdx.x * per;
    int r1 = min(r0 + per, total);
    for (int r = r0; r < r1; r++) {
        __syncthreads();
        if (g < 16) xs[g] = ((const float4*)(enc + (size_t)r * 64))[g];
        __syncthreads();
        float acc = bias;
#pragma unroll
        for (int e4 = 0; e4 < 16; e4++) {
            float4 x = xs[e4];
            acc += w[e4*4+0]*x.x + w[e4*4+1]*x.y + w[e4*4+2]*x.z + w[e4*4+3]*x.w;
        }
        g_genc[(size_t)r * G4 + g] = acc;
    }
}

// ---------------- kernel 3: software-pipelined recurrence -------------------
__global__ __launch_bounds__(256, 1) void rec_kernel(
    const float* __restrict__ s0,    // (1,16)
    const float* __restrict__ h0,    // (2,16)
    const float* __restrict__ c0,    // (2,128)
    const float* __restrict__ Wih0,  // (512,80)
    const float* __restrict__ Whh0,  // (512,16)
    const float* __restrict__ Whr0,  // (16,128)
    const float* __restrict__ Wih1,  // (512,16)
    const float* __restrict__ Whh1,  // (512,16)
    const float* __restrict__ bih1,  // (512)
    const float* __restrict__ bhh1,  // (512)
    const float* __restrict__ Whr1,  // (16,128)
    float* __restrict__ out)         // (B,FUT,N,O)
{
    const int b   = blockIdx.x;
    const int tid = threadIdx.x;
    const int k   = tid & 127;
    const bool isL0 = tid < 128;

    __shared__ __align__(16) float s_last[16];   // h2 carry (seeded with s0)
    __shared__ __align__(16) float s_h1[16];
    __shared__ __align__(16) float s_h2[16];     // h2 (seeded with h0[1])
    __shared__ __align__(16) float s_nm[2][16];  // ping-pong by node parity
    __shared__ __align__(16) float s_hf0[128];
    __shared__ __align__(16) float s_hf1[128];

    // packed weights (per gate q, 16 ull = 32 floats):
    //  L0: [0:8) = W_ih0 loop cols (mult. last / nm), [8:16) = W_hh0 (mult. h1)
    //  L1: [0:8) = W_ih1 (mult. h1),                  [8:16) = W_hh1 (mult. h2)
    ull w2[4][16];
    ull wpr2[16];                    // 32-elem projection segment (k<64 only)
    float bias[4];
    float c_reg;

    {
        const int po = k >> 2, ps = k & 3;      // proj output / segment (k<64)
        if (isL0) {
#pragma unroll
            for (int q = 0; q < 4; q++) {
                int g = q * 128 + k;
#pragma unroll
                for (int j = 0; j < 8; j++) {
                    w2[q][j]     = pk(Wih0[g * 80 + 64 + 2*j], Wih0[g * 80 + 64 + 2*j + 1]);
                    w2[q][8 + j] = pk(Whh0[g * 16 + 2*j],      Whh0[g * 16 + 2*j + 1]);
                }
                bias[q] = 0.f;
            }
            c_reg = c0[k];
            if (k < 64) {
#pragma unroll
                for (int j = 0; j < 16; j++)
                    wpr2[j] = pk(Whr0[po * 128 + ps * 32 + 2*j],
                                 Whr0[po * 128 + ps * 32 + 2*j + 1]);
            }
        } else {
#pragma unroll
            for (int q = 0; q < 4; q++) {
                int g = q * 128 + k;
#pragma unroll
                for (int j = 0; j < 8; j++) {
                    w2[q][j]     = pk(Wih1[g * 16 + 2*j], Wih1[g * 16 + 2*j + 1]);
                    w2[q][8 + j] = pk(Whh1[g * 16 + 2*j], Whh1[g * 16 + 2*j + 1]);
                }
                bias[q] = bih1[g] + bhh1[g];
            }
            c_reg = c0[128 + k];
            if (k < 64) {
#pragma unroll
                for (int j = 0; j < 16; j++)
                    wpr2[j] = pk(Whr1[po * 128 + ps * 32 + 2*j],
                                 Whr1[po * 128 + ps * 32 + 2*j + 1]);
            }
        }
    }

    if (tid < 16) {
        s_last[tid]   = s0[tid];
        s_h1[tid]     = h0[tid];
        s_h2[tid]     = h0[16 + tid];
        s_nm[0][tid]  = g_nm[(size_t)b * NNODE * OO + tid];
    }
    __syncthreads();

    float partial[4];                 // precomputed off-cycle gate part
    float genc_c[4], genc_n[4], gnm[4];
    float nm_pref = 0.f;

    if (isL0) {
        size_t base = (size_t)b * NNODE * G4 + k;
#pragma unroll
        for (int q = 0; q < 4; q++) genc_c[q] = g_genc[base + q * 128];
#pragma unroll
        for (int q = 0; q < 4; q++) genc_n[q] = g_genc[base + G4 + q * 128]; // node 1
        if (k < 16) nm_pref = g_nm[((size_t)b * NNODE + 1) * OO + k];
        // gnm(node0) + partial0(t=0) = genc + gnm + Whh0@h1_0
        {
            ull a[4];
#pragma unroll
            for (int q = 0; q < 4; q++) a[q] = pk(0.f, 0.f);
            const ulonglong2* nm4 = (const ulonglong2*)s_nm[0];
#pragma unroll
            for (int i = 0; i < 4; i++) {
                ulonglong2 xx = nm4[i];
#pragma unroll
                for (int q = 0; q < 4; q++) {
                    ffma2(a[q], w2[q][2*i],     xx.x);
                    ffma2(a[q], w2[q][2*i + 1], xx.y);
                }
            }
#pragma unroll
            for (int q = 0; q < 4; q++) gnm[q] = hsum(a[q]);
        }
        {
            ull a[4];
#pragma unroll
            for (int q = 0; q < 4; q++) a[q] = pk(genc_c[q] + gnm[q], 0.f);
            const ulonglong2* h14 = (const ulonglong2*)s_h1;
#pragma unroll
            for (int i = 0; i < 4; i++) {
                ulonglong2 xx = h14[i];
#pragma unroll
                for (int q = 0; q < 4; q++) {
                    ffma2(a[q], w2[q][8 + 2*i], xx.x);
                    ffma2(a[q], w2[q][9 + 2*i], xx.y);
                }
            }
#pragma unroll
            for (int q = 0; q < 4; q++) partial[q] = hsum(a[q]);
        }
    } else {
        // partial1(t=0) = bias + Whh1@h2_0
        ull a[4];
#pragma unroll
        for (int q = 0; q < 4; q++) a[q] = pk(bias[q], 0.f);
        const ulonglong2* h24 = (const ulonglong2*)s_h2;
#pragma unroll
        for (int i = 0; i < 4; i++) {
            ulonglong2 xx = h24[i];
#pragma unroll
            for (int q = 0; q < 4; q++) {
                ffma2(a[q], w2[q][8 + 2*i], xx.x);
                ffma2(a[q], w2[q][9 + 2*i], xx.y);
            }
        }
#pragma unroll
        for (int q = 0; q < 4; q++) partial[q] = hsum(a[q]);
        BAR_H2_ARRIVE();              // publish initial state to L0
    }

    int n = 0, f = 0;
    const int po = k >> 2, ps = k & 3;

    for (int t = 0; t < TOT; t++) {
        if (isL0) {
            // ================= layer 0 =================
            BAR_H2_SYNC();                        // h2_{t-1} (s_last) ready
            ull acc[4];
#pragma unroll
            for (int q = 0; q < 4; q++) acc[q] = pk(partial[q], 0.f);
            const ulonglong2* x4 = (const ulonglong2*)s_last;
#pragma unroll
            for (int i = 0; i < 4; i++) {
                ulonglong2 xx = x4[i];
#pragma unroll
                for (int q = 0; q < 4; q++) {
                    ffma2(acc[q], w2[q][2*i],     xx.x);
                    ffma2(acc[q], w2[q][2*i + 1], xx.y);
                }
            }
            float ig = sigm(hsum(acc[0]));
            float fg = sigm(hsum(acc[1]));
            float gg = tanhfast(hsum(acc[2]));
            float og = sigm(hsum(acc[3]));
            c_reg = fg * c_reg + ig * gg;
            s_hf0[k] = og * tanhfast(c_reg);
            BAR_L0();                             // hf0 visible in L0

            if (k < 64) {                         // proj h1: 4 threads/output
                const ulonglong2* hf4 = (const ulonglong2*)(s_hf0 + ps * 32);
                ull pa = pk(0.f, 0.f), pb = pk(0.f, 0.f);
#pragma unroll
                for (int i = 0; i < 4; i++) {
                    ulonglong2 xa = hf4[2*i], xb = hf4[2*i + 1];
                    ffma2(pa, wpr2[4*i + 0], xa.x);
                    ffma2(pa, wpr2[4*i + 1], xa.y);
                    ffma2(pb, wpr2[4*i + 2], xb.x);
                    ffma2(pb, wpr2[4*i + 3], xb.y);
                }
                float p = hsum(pa) + hsum(pb);
                p += __shfl_xor_sync(0xffffffffu, p, 2);
                p += __shfl_xor_sync(0xffffffffu, p, 1);
                if (ps == 0) s_h1[po] = p;
            }
            BAR_H1_ARRIVE();                      // release L1 (waits all 128)
            BAR_L0();                             // h1 visible in L0

            // ---- off-cycle prep for step t+1 ----
            int f1 = f + 1, n1 = n;
            if (f1 == FUT) { f1 = 0; n1 = n + 1; }
            if (n1 < NNODE) {
                if (f1 == 0) {                    // node boundary
                    if (k < 16) {
                        s_nm[n1 & 1][k] = nm_pref;
                        int np = (n1 + 1 < NNODE) ? n1 + 1 : n1;
                        nm_pref = g_nm[((size_t)b * NNODE + np) * OO + k];
                    }
                    BAR_L0();
                    ull a[4];
#pragma unroll
                    for (int q = 0; q < 4; q++) a[q] = pk(0.f, 0.f);
                    const ulonglong2* nm4 = (const ulonglong2*)s_nm[n1 & 1];
#pragma unroll
                    for (int i = 0; i < 4; i++) {
                        ulonglong2 xx = nm4[i];
#pragma unroll
                        for (int q = 0; q < 4; q++) {
                            ffma2(a[q], w2[q][2*i],     xx.x);
                            ffma2(a[q], w2[q][2*i + 1], xx.y);
                        }
                    }
#pragma unroll
                    for (int q = 0; q < 4; q++) gnm[q] = hsum(a[q]);
#pragma unroll
                    for (int q = 0; q < 4; q++) genc_c[q] = genc_n[q];
                    int np = (n1 + 1 < NNODE) ? n1 + 1 : n1;
                    size_t base = ((size_t)b * NNODE + np) * G4 + k;
#pragma unroll
                    for (int q = 0; q < 4; q++) genc_n[q] = g_genc[base + q * 128];
                }
                ull a[4];
#pragma unroll
                for (int q = 0; q < 4; q++) a[q] = pk(genc_c[q] + gnm[q], 0.f);
                const ulonglong2* h14 = (const ulonglong2*)s_h1;
#pragma unroll
                for (int i = 0; i < 4; i++) {
                    ulonglong2 xx = h14[i];
#pragma unroll
                    for (int q = 0; q < 4; q++) {
                        ffma2(a[q], w2[q][8 + 2*i], xx.x);
                        ffma2(a[q], w2[q][9 + 2*i], xx.y);
                    }
                }
#pragma unroll
                for (int q = 0; q < 4; q++) partial[q] = hsum(a[q]);
            }
            f = f1; n = n1;
        } else {
            // ================= layer 1 =================
            BAR_H1_SYNC();                        // h1_t ready
            ull acc[4];
#pragma unroll
            for (int q = 0; q < 4; q++) acc[q] = pk(partial[q], 0.f);
            const ulonglong2* h14 = (const ulonglong2*)s_h1;
#pragma unroll
            for (int i = 0; i < 4; i++) {
                ulonglong2 xx = h14[i];
#pragma unroll
                for (int q = 0; q < 4; q++) {
                    ffma2(acc[q], w2[q][2*i],     xx.x);
                    ffma2(acc[q], w2[q][2*i + 1], xx.y);
                }
            }
            float ig = sigm(hsum(acc[0]));
            float fg = sigm(hsum(acc[1]));
            float gg = tanhfast(hsum(acc[2]));
            float og = sigm(hsum(acc[3]));
            c_reg = fg * c_reg + ig * gg;
            s_hf1[k] = og * tanhfast(c_reg);
            BAR_L1();                             // hf1 visible in L1

            float p = 0.f;
            if (k < 64) {                         // proj h2
                const ulonglong2* hf4 = (const ulonglong2*)(s_hf1 + ps * 32);
                ull pa = pk(0.f, 0.f), pb = pk(0.f, 0.f);
#pragma unroll
                for (int i = 0; i < 4; i++) {
                    ulonglong2 xa = hf4[2*i], xb = hf4[2*i + 1];
                    ffma2(pa, wpr2[4*i + 0], xa.x);
                    ffma2(pa, wpr2[4*i + 1], xa.y);
                    ffma2(pb, wpr2[4*i + 2], xb.x);
                    ffma2(pb, wpr2[4*i + 3], xb.y);
                }
                p = hsum(pa) + hsum(pb);
                p += __shfl_xor_sync(0xffffffffu, p, 2);
                p += __shfl_xor_sync(0xffffffffu, p, 1);
                if (ps == 0) { s_h2[po] = p; s_last[po] = p; }
            }
            BAR_H2_ARRIVE();                      // release L0

            if (k < 64 && ps == 0)                // output (off-cycle)
                out[(((size_t)b * FUT + f) * NNODE + n) * OO + po]
                    = p + s_nm[n & 1][po];
            BAR_L1();                             // h2 visible in L1

            // ---- off-cycle prep: partial1 for t+1 ----
            ull a[4];
#pragma unroll
            for (int q = 0; q < 4; q++) a[q] = pk(bias[q], 0.f);
            const ulonglong2* h24 = (const ulonglong2*)s_h2;
#pragma unroll
            for (int i = 0; i < 4; i++) {
                ulonglong2 xx = h24[i];
#pragma unroll
                for (int q = 0; q < 4; q++) {
                    ffma2(a[q], w2[q][8 + 2*i], xx.x);
                    ffma2(a[q], w2[q][9 + 2*i], xx.y);
                }
            }
#pragma unroll
            for (int q = 0; q < 4; q++) partial[q] = hsum(a[q]);
            if (++f == FUT) { f = 0; ++n; }
        }
    }
}

// ---------------- launch ----------------------------------------------------
extern "C" void kernel_launch(void* const* d_in, const int* in_sizes, int n_in,
                              void* d_out, int out_size)
{
    const float* enc  = (const float*)d_in[0];   // (64,1,1000,64)
    const float* mean = (const float*)d_in[1];   // (64,12,1000,16)
    const float* s    = (const float*)d_in[2];   // (1,16)
    const float* h0   = (const float*)d_in[3];   // (2,16)
    const float* c0   = (const float*)d_in[4];   // (2,128)
    const float* Wih0 = (const float*)d_in[5];   // (512,80)
    const float* Whh0 = (const float*)d_in[6];   // (512,16)
    const float* bih0 = (const float*)d_in[7];   // (512)
    const float* bhh0 = (const float*)d_in[8];   // (512)
    const float* Whr0 = (const float*)d_in[9];   // (16,128)
    const float* Wih1 = (const float*)d_in[10];  // (512,16)
    const float* Whh1 = (const float*)d_in[11];  // (512,16)
    const float* bih1 = (const float*)d_in[12];  // (512)
    const float* bhh1 = (const float*)d_in[13];  // (512)
    const float* Whr1 = (const float*)d_in[14];  // (16,128)
    float* out = (float*)d_out;                  // (64,12,1000,16) fp32

    nm_kernel<<<(BB * NNODE * 4 + 255) / 256, 256>>>(mean);
    genc_kernel<<<148, 512>>>(enc, Wih0, bih0, bhh0);
    rec_kernel<<<BB, 256>>>(s, h0, c0, Wih0, Whh0, Whr0,
                            Wih1, Whh1, bih1, bhh1, Whr1, out);
}

// round 7
// speedup vs baseline: 1.7975x; 1.1299x over previous
#include <cuda_runtime.h>
#include <cstddef>

#define BB  64
#define NNODE 1000
#define EE  64
#define OO  16
#define HH  128
#define FUT 12
#define G4  512   // 4*H
#define TOT (NNODE * FUT)

typedef unsigned long long ull;

// ---------------- device scratch (static, no allocations) ----------------
__device__ float g_nm[(size_t)BB * NNODE * OO];            // 4 MB  : node_mean
__device__ float g_genc[(size_t)BB * NNODE * G4];          // 131 MB: enc@W_e^T + b_ih0 + b_hh0

// ---------------- packed f32x2 helpers ------------------------------------
__device__ __forceinline__ void ffma2(ull& acc, ull a, ull b) {
    asm("fma.rn.f32x2 %0, %1, %2, %0;" : "+l"(acc) : "l"(a), "l"(b));
}
__device__ __forceinline__ ull pk(float lo, float hi) {
    ull r;
    asm("mov.b64 %0, {%1, %2};" : "=l"(r) : "f"(lo), "f"(hi));
    return r;
}
__device__ __forceinline__ float hsum(ull v) {
    float lo, hi;
    asm("mov.b64 {%0, %1}, %2;" : "=f"(lo), "=f"(hi) : "l"(v));
    return lo + hi;
}

// ---------------- MUFU.TANH-based activations ------------------------------
__device__ __forceinline__ float tanhapx(float x) {
    float r;
    asm("tanh.approx.f32 %0, %1;" : "=f"(r) : "f"(x));
    return r;
}
__device__ __forceinline__ float sigm(float x) {
    return fmaf(0.5f, tanhapx(0.5f * x), 0.5f);
}
__device__ __forceinline__ float tanhfast(float x) {
    return tanhapx(x);
}

// named barriers: 1/2 intra-group (128), 3/4 producer->consumer (256 total)
#define BAR_L0()        asm volatile("bar.sync 1, 128;"   ::: "memory")
#define BAR_L1()        asm volatile("bar.sync 2, 128;"   ::: "memory")
#define BAR_H2_SYNC()   asm volatile("bar.sync 3, 256;"   ::: "memory")
#define BAR_H2_ARRIVE() asm volatile("bar.arrive 3, 256;" ::: "memory")
#define BAR_H1_SYNC()   asm volatile("bar.sync 4, 256;"   ::: "memory")
#define BAR_H1_ARRIVE() asm volatile("bar.arrive 4, 256;" ::: "memory")

// ---------------- kernel 1: node_mean = mean(mean, axis=FUT) -------------
__global__ void nm_kernel(const float* __restrict__ mean) {
    int idx = blockIdx.x * blockDim.x + threadIdx.x;      // over B*N*4 float4s
    if (idx >= BB * NNODE * 4) return;
    int q = idx & 3;
    int n = (idx >> 2) % NNODE;
    int b = idx / (NNODE * 4);
    float4 s = make_float4(0.f, 0.f, 0.f, 0.f);
    const float4* m4 = (const float4*)mean;
#pragma unroll
    for (int f = 0; f < FUT; f++) {
        float4 v = m4[(((size_t)b * FUT + f) * NNODE + n) * 4 + q];
        s.x += v.x; s.y += v.y; s.z += v.z; s.w += v.w;
    }
    const float inv = 1.0f / FUT;
    s.x *= inv; s.y *= inv; s.z *= inv; s.w *= inv;
    ((float4*)g_nm)[idx] = s;
}

// ---------------- kernel 2: G_enc precompute ------------------------------
__global__ __launch_bounds__(512) void genc_kernel(
    const float* __restrict__ enc,
    const float* __restrict__ Wih0,
    const float* __restrict__ bih0,
    const float* __restrict__ bhh0)
{
    int g = threadIdx.x;                                   // gate 0..511
    float w[64];
#pragma unroll
    for (int e = 0; e < 64; e++) w[e] = Wih0[g * 80 + e];
    float bias = bih0[g] + bhh0[g];

    __shared__ __align__(16) float4 xs[16];                // one enc row (64 f)
    int total = BB * NNODE;
    int per = (total + gridDim.x - 1) / gridDim.x;
    int r0 = blockIdx.x * per;
    int r1 = min(r0 + per, total);
    for (int r = r0; r < r1; r++) {
        __syncthreads();
        if (g < 16) xs[g] = ((const float4*)(enc + (size_t)r * 64))[g];
        __syncthreads();
        float acc = bias;
#pragma unroll
        for (int e4 = 0; e4 < 16; e4++) {
            float4 x = xs[e4];
            acc += w[e4*4+0]*x.x + w[e4*4+1]*x.y + w[e4*4+2]*x.z + w[e4*4+3]*x.w;
        }
        g_genc[(size_t)r * G4 + g] = acc;
    }
}

// ---------------- kernel 3: software-pipelined recurrence -------------------
__global__ __launch_bounds__(256, 1) void rec_kernel(
    const float* __restrict__ s0,    // (1,16)
    const float* __restrict__ h0,    // (2,16)
    const float* __restrict__ c0,    // (2,128)
    const float* __restrict__ Wih0,  // (512,80)
    const float* __restrict__ Whh0,  // (512,16)
    const float* __restrict__ Whr0,  // (16,128)
    const float* __restrict__ Wih1,  // (512,16)
    const float* __restrict__ Whh1,  // (512,16)
    const float* __restrict__ bih1,  // (512)
    const float* __restrict__ bhh1,  // (512)
    const float* __restrict__ Whr1,  // (16,128)
    float* __restrict__ out)         // (B,FUT,N,O)
{
    const int b   = blockIdx.x;
    const int tid = threadIdx.x;
    const int k   = tid & 127;
    const bool isL0 = tid < 128;

    __shared__ __align__(16) float s_last[16];   // h2 carry (seeded with s0)
    __shared__ __align__(16) float s_h1[16];
    __shared__ __align__(16) float s_h2[16];     // h2 (seeded with h0[1])
    __shared__ __align__(16) float s_nm[2][16];  // ping-pong by node parity
    __shared__ __align__(16) float s_hf0[128];
    __shared__ __align__(16) float s_hf1[128];

    // packed weights (per gate q, 16 ull = 32 floats):
    //  L0: [0:8) = W_ih0 loop cols (mult. last / nm), [8:16) = W_hh0 (mult. h1)
    //  L1: [0:8) = W_ih1 (mult. h1),                  [8:16) = W_hh1 (mult. h2)
    ull w2[4][16];
    ull wpr2[16];                    // 32-elem projection segment (k<64 only)
    float bias[4];
    float c_reg;

    {
        const int po = k >> 2, ps = k & 3;      // proj output / segment (k<64)
        if (isL0) {
#pragma unroll
            for (int q = 0; q < 4; q++) {
                int g = q * 128 + k;
#pragma unroll
                for (int j = 0; j < 8; j++) {
                    w2[q][j]     = pk(Wih0[g * 80 + 64 + 2*j], Wih0[g * 80 + 64 + 2*j + 1]);
                    w2[q][8 + j] = pk(Whh0[g * 16 + 2*j],      Whh0[g * 16 + 2*j + 1]);
                }
                bias[q] = 0.f;
            }
            c_reg = c0[k];
            if (k < 64) {
#pragma unroll
                for (int j = 0; j < 16; j++)
                    wpr2[j] = pk(Whr0[po * 128 + ps * 32 + 2*j],
                                 Whr0[po * 128 + ps * 32 + 2*j + 1]);
            }
        } else {
#pragma unroll
            for (int q = 0; q < 4; q++) {
                int g = q * 128 + k;
#pragma unroll
                for (int j = 0; j < 8; j++) {
                    w2[q][j]     = pk(Wih1[g * 16 + 2*j], Wih1[g * 16 + 2*j + 1]);
                    w2[q][8 + j] = pk(Whh1[g * 16 + 2*j], Whh1[g * 16 + 2*j + 1]);
                }
                bias[q] = bih1[g] + bhh1[g];
            }
            c_reg = c0[128 + k];
            if (k < 64) {
#pragma unroll
                for (int j = 0; j < 16; j++)
                    wpr2[j] = pk(Whr1[po * 128 + ps * 32 + 2*j],
                                 Whr1[po * 128 + ps * 32 + 2*j + 1]);
            }
        }
    }

    if (tid < 16) {
        s_last[tid]   = s0[tid];
        s_h1[tid]     = h0[tid];
        s_h2[tid]     = h0[16 + tid];
        s_nm[0][tid]  = g_nm[(size_t)b * NNODE * OO + tid];
    }
    __syncthreads();

    float partial[4];                 // precomputed off-cycle gate part
    float genc_c[4], genc_n[4], gnm[4];
    float nm_pref = 0.f;

    if (isL0) {
        size_t base = (size_t)b * NNODE * G4 + k;
#pragma unroll
        for (int q = 0; q < 4; q++) genc_c[q] = g_genc[base + q * 128];
#pragma unroll
        for (int q = 0; q < 4; q++) genc_n[q] = g_genc[base + G4 + q * 128]; // node 1
        if (k < 16) nm_pref = g_nm[((size_t)b * NNODE + 1) * OO + k];
        // gnm(node0) + partial0(t=0) = genc + gnm + Whh0@h1_0
        {
            ull a[4];
#pragma unroll
            for (int q = 0; q < 4; q++) a[q] = pk(0.f, 0.f);
            const ulonglong2* nm4 = (const ulonglong2*)s_nm[0];
#pragma unroll
            for (int i = 0; i < 4; i++) {
                ulonglong2 xx = nm4[i];
#pragma unroll
                for (int q = 0; q < 4; q++) {
                    ffma2(a[q], w2[q][2*i],     xx.x);
                    ffma2(a[q], w2[q][2*i + 1], xx.y);
                }
            }
#pragma unroll
            for (int q = 0; q < 4; q++) gnm[q] = hsum(a[q]);
        }
        {
            ull a[4];
#pragma unroll
            for (int q = 0; q < 4; q++) a[q] = pk(genc_c[q] + gnm[q], 0.f);
            const ulonglong2* h14 = (const ulonglong2*)s_h1;
#pragma unroll
            for (int i = 0; i < 4; i++) {
                ulonglong2 xx = h14[i];
#pragma unroll
                for (int q = 0; q < 4; q++) {
                    ffma2(a[q], w2[q][8 + 2*i], xx.x);
                    ffma2(a[q], w2[q][9 + 2*i], xx.y);
                }
            }
#pragma unroll
            for (int q = 0; q < 4; q++) partial[q] = hsum(a[q]);
        }
    } else {
        // partial1(t=0) = bias + Whh1@h2_0
        ull a[4];
#pragma unroll
        for (int q = 0; q < 4; q++) a[q] = pk(bias[q], 0.f);
        const ulonglong2* h24 = (const ulonglong2*)s_h2;
#pragma unroll
        for (int i = 0; i < 4; i++) {
            ulonglong2 xx = h24[i];
#pragma unroll
            for (int q = 0; q < 4; q++) {
                ffma2(a[q], w2[q][8 + 2*i], xx.x);
                ffma2(a[q], w2[q][9 + 2*i], xx.y);
            }
        }
#pragma unroll
        for (int q = 0; q < 4; q++) partial[q] = hsum(a[q]);
        BAR_H2_ARRIVE();              // publish initial state to L0
    }

    int n = 0, f = 0;
    const int po = k >> 2, ps = k & 3;

    for (int t = 0; t < TOT; t++) {
        if (isL0) {
            // ================= layer 0 =================
            BAR_H2_SYNC();                        // h2_{t-1} (s_last) ready
            ull acc[4];
#pragma unroll
            for (int q = 0; q < 4; q++) acc[q] = pk(partial[q], 0.f);
            const ulonglong2* x4 = (const ulonglong2*)s_last;
#pragma unroll
            for (int i = 0; i < 4; i++) {
                ulonglong2 xx = x4[i];
#pragma unroll
                for (int q = 0; q < 4; q++) {
                    ffma2(acc[q], w2[q][2*i],     xx.x);
                    ffma2(acc[q], w2[q][2*i + 1], xx.y);
                }
            }
            float ig = sigm(hsum(acc[0]));
            float fg = sigm(hsum(acc[1]));
            float gg = tanhfast(hsum(acc[2]));
            float og = sigm(hsum(acc[3]));
            c_reg = fg * c_reg + ig * gg;
            s_hf0[k] = og * tanhfast(c_reg);
            BAR_L0();                             // hf0 visible in L0

            if (k < 64) {                         // proj h1: 4 threads/output
                const ulonglong2* hf4 = (const ulonglong2*)(s_hf0 + ps * 32);
                ull pa = pk(0.f, 0.f), pb = pk(0.f, 0.f);
#pragma unroll
                for (int i = 0; i < 4; i++) {
                    ulonglong2 xa = hf4[2*i], xb = hf4[2*i + 1];
                    ffma2(pa, wpr2[4*i + 0], xa.x);
                    ffma2(pa, wpr2[4*i + 1], xa.y);
                    ffma2(pb, wpr2[4*i + 2], xb.x);
                    ffma2(pb, wpr2[4*i + 3], xb.y);
                }
                float p = hsum(pa) + hsum(pb);
                p += __shfl_xor_sync(0xffffffffu, p, 2);
                p += __shfl_xor_sync(0xffffffffu, p, 1);
                if (ps == 0) s_h1[po] = p;
            }
            BAR_H1_ARRIVE();                      // release L1 (waits all 128)
            BAR_L0();                             // h1 visible in L0

            // ---- off-cycle prep for step t+1 ----
            int f1 = f + 1, n1 = n;
            if (f1 == FUT) { f1 = 0; n1 = n + 1; }
            if (n1 < NNODE) {
                if (f1 == 0) {                    // node boundary
                    if (k < 16) {
                        s_nm[n1 & 1][k] = nm_pref;
                        int np = (n1 + 1 < NNODE) ? n1 + 1 : n1;
                        nm_pref = g_nm[((size_t)b * NNODE + np) * OO + k];
                    }
                    BAR_L0();
                    ull a[4];
#pragma unroll
                    for (int q = 0; q < 4; q++) a[q] = pk(0.f, 0.f);
                    const ulonglong2* nm4 = (const ulonglong2*)s_nm[n1 & 1];
#pragma unroll
                    for (int i = 0; i < 4; i++) {
                        ulonglong2 xx = nm4[i];
#pragma unroll
                        for (int q = 0; q < 4; q++) {
                            ffma2(a[q], w2[q][2*i],     xx.x);
                            ffma2(a[q], w2[q][2*i + 1], xx.y);
                        }
                    }
#pragma unroll
                    for (int q = 0; q < 4; q++) gnm[q] = hsum(a[q]);
#pragma unroll
                    for (int q = 0; q < 4; q++) genc_c[q] = genc_n[q];
                    int np = (n1 + 1 < NNODE) ? n1 + 1 : n1;
                    size_t base = ((size_t)b * NNODE + np) * G4 + k;
#pragma unroll
                    for (int q = 0; q < 4; q++) genc_n[q] = g_genc[base + q * 128];
                }
                ull a[4];
#pragma unroll
                for (int q = 0; q < 4; q++) a[q] = pk(genc_c[q] + gnm[q], 0.f);
                const ulonglong2* h14 = (const ulonglong2*)s_h1;
#pragma unroll
                for (int i = 0; i < 4; i++) {
                    ulonglong2 xx = h14[i];
#pragma unroll
                    for (int q = 0; q < 4; q++) {
                        ffma2(a[q], w2[q][8 + 2*i], xx.x);
                        ffma2(a[q], w2[q][9 + 2*i], xx.y);
                    }
                }
#pragma unroll
                for (int q = 0; q < 4; q++) partial[q] = hsum(a[q]);
            }
            f = f1; n = n1;
        } else {
            // ================= layer 1 =================
            BAR_H1_SYNC();                        // h1_t ready
            ull acc[4];
#pragma unroll
            for (int q = 0; q < 4; q++) acc[q] = pk(partial[q], 0.f);
            const ulonglong2* h14 = (const ulonglong2*)s_h1;
#pragma unroll
            for (int i = 0; i < 4; i++) {
                ulonglong2 xx = h14[i];
#pragma unroll
                for (int q = 0; q < 4; q++) {
                    ffma2(acc[q], w2[q][2*i],     xx.x);
                    ffma2(acc[q], w2[q][2*i + 1], xx.y);
                }
            }
            float ig = sigm(hsum(acc[0]));
            float fg = sigm(hsum(acc[1]));
            float gg = tanhfast(hsum(acc[2]));
            float og = sigm(hsum(acc[3]));
            c_reg = fg * c_reg + ig * gg;
            s_hf1[k] = og * tanhfast(c_reg);
            BAR_L1();                             // hf1 visible in L1

            float p = 0.f;
            if (k < 64) {                         // proj h2
                const ulonglong2* hf4 = (const ulonglong2*)(s_hf1 + ps * 32);
                ull pa = pk(0.f, 0.f), pb = pk(0.f, 0.f);
#pragma unroll
                for (int i = 0; i < 4; i++) {
                    ulonglong2 xa = hf4[2*i], xb = hf4[2*i + 1];
                    ffma2(pa, wpr2[4*i + 0], xa.x);
                    ffma2(pa, wpr2[4*i + 1], xa.y);
                    ffma2(pb, wpr2[4*i + 2], xb.x);
                    ffma2(pb, wpr2[4*i + 3], xb.y);
                }
                p = hsum(pa) + hsum(pb);
                p += __shfl_xor_sync(0xffffffffu, p, 2);
                p += __shfl_xor_sync(0xffffffffu, p, 1);
                if (ps == 0) { s_h2[po] = p; s_last[po] = p; }
            }
            BAR_H2_ARRIVE();                      // release L0

            if (k < 64 && ps == 0)                // output (off-cycle)
                out[(((size_t)b * FUT + f) * NNODE + n) * OO + po]
                    = p + s_nm[n & 1][po];
            BAR_L1();                             // h2 visible in L1

            // ---- off-cycle prep: partial1 for t+1 ----
            ull a[4];
#pragma unroll
            for (int q = 0; q < 4; q++) a[q] = pk(bias[q], 0.f);
            const ulonglong2* h24 = (const ulonglong2*)s_h2;
#pragma unroll
            for (int i = 0; i < 4; i++) {
                ulonglong2 xx = h24[i];
#pragma unroll
                for (int q = 0; q < 4; q++) {
                    ffma2(a[q], w2[q][8 + 2*i], xx.x);
                    ffma2(a[q], w2[q][9 + 2*i], xx.y);
                }
            }
#pragma unroll
            for (int q = 0; q < 4; q++) partial[q] = hsum(a[q]);
            if (++f == FUT) { f = 0; ++n; }
        }
    }
}

// ---------------- launch ----------------------------------------------------
extern "C" void kernel_launch(void* const* d_in, const int* in_sizes, int n_in,
                              void* d_out, int out_size)
{
    const float* enc  = (const float*)d_in[0];   // (64,1,1000,64)
    const float* mean = (const float*)d_in[1];   // (64,12,1000,16)
    const float* s    = (const float*)d_in[2];   // (1,16)
    const float* h0   = (const float*)d_in[3];   // (2,16)
    const float* c0   = (const float*)d_in[4];   // (2,128)
    const float* Wih0 = (const float*)d_in[5];   // (512,80)
    const float* Whh0 = (const float*)d_in[6];   // (512,16)
    const float* bih0 = (const float*)d_in[7];   // (512)
    const float* bhh0 = (const float*)d_in[8];   // (512)
    const float* Whr0 = (const float*)d_in[9];   // (16,128)
    const float* Wih1 = (const float*)d_in[10];  // (512,16)
    const float* Whh1 = (const float*)d_in[11];  // (512,16)
    const float* bih1 = (const float*)d_in[12];  // (512)
    const float* bhh1 = (const float*)d_in[13];  // (512)
    const float* Whr1 = (const float*)d_in[14];  // (16,128)
    float* out = (float*)d_out;                  // (64,12,1000,16) fp32

    nm_kernel<<<(BB * NNODE * 4 + 255) / 256, 256>>>(mean);
    genc_kernel<<<148, 512>>>(enc, Wih0, bih0, bhh0);
    rec_kernel<<<BB, 256>>>(s, h0, c0, Wih0, Whh0, Whr0,
                            Wih1, Whh1, bih1, bhh1, Whr1, out);
}

// round 8
// speedup vs baseline: 1.8039x; 1.0035x over previous
#include <cuda_runtime.h>
#include <cstddef>

#define BB  64
#define NNODE 1000
#define EE  64
#define OO  16
#define HH  128
#define FUT 12
#define G4  512   // 4*H
#define TOT (NNODE * FUT)

typedef unsigned long long ull;

// ---------------- device scratch (static, no allocations) ----------------
__device__ float g_nm[(size_t)BB * NNODE * OO];            // 4 MB  : node_mean
__device__ float g_genc[(size_t)BB * NNODE * G4];          // 131 MB: enc@W_e^T + b_ih0 + b_hh0

// ---------------- packed f32x2 helpers ------------------------------------
__device__ __forceinline__ void ffma2(ull& acc, ull a, ull b) {
    asm("fma.rn.f32x2 %0, %1, %2, %0;" : "+l"(acc) : "l"(a), "l"(b));
}
__device__ __forceinline__ ull pk(float lo, float hi) {
    ull r;
    asm("mov.b64 %0, {%1, %2};" : "=l"(r) : "f"(lo), "f"(hi));
    return r;
}
__device__ __forceinline__ float hsum(ull v) {
    float lo, hi;
    asm("mov.b64 {%0, %1}, %2;" : "=f"(lo), "=f"(hi) : "l"(v));
    return lo + hi;
}

// ---------------- MUFU.TANH-based activations ------------------------------
__device__ __forceinline__ float tanhapx(float x) {
    float r;
    asm("tanh.approx.f32 %0, %1;" : "=f"(r) : "f"(x));
    return r;
}
// input is PRE-HALVED (weights scaled by 0.5): sigmoid(2x~) = 0.5*tanh(x~)+0.5
__device__ __forceinline__ float sigm_h(float xh) {
    return fmaf(0.5f, tanhapx(xh), 0.5f);
}

// barriers: 1/2 intra-group (128); 3/4 two-sided rendezvous (256)
#define BAR1()        asm volatile("bar.sync 1, 128;"   ::: "memory")
#define BAR2()        asm volatile("bar.sync 2, 128;"   ::: "memory")
#define SYNC3()       asm volatile("bar.sync 3, 256;"   ::: "memory")
#define ARRIVE3()     asm volatile("bar.arrive 3, 256;" ::: "memory")
#define SYNC4()       asm volatile("bar.sync 4, 256;"   ::: "memory")

// ---------------- kernel 1: node_mean = mean(mean, axis=FUT) -------------
__global__ void nm_kernel(const float* __restrict__ mean) {
    int idx = blockIdx.x * blockDim.x + threadIdx.x;      // over B*N*4 float4s
    if (idx >= BB * NNODE * 4) return;
    int q = idx & 3;
    int n = (idx >> 2) % NNODE;
    int b = idx / (NNODE * 4);
    float4 s = make_float4(0.f, 0.f, 0.f, 0.f);
    const float4* m4 = (const float4*)mean;
#pragma unroll
    for (int f = 0; f < FUT; f++) {
        float4 v = m4[(((size_t)b * FUT + f) * NNODE + n) * 4 + q];
        s.x += v.x; s.y += v.y; s.z += v.z; s.w += v.w;
    }
    const float inv = 1.0f / FUT;
    s.x *= inv; s.y *= inv; s.z *= inv; s.w *= inv;
    ((float4*)g_nm)[idx] = s;
}

// ---------------- kernel 2: G_enc precompute ------------------------------
__global__ __launch_bounds__(512) void genc_kernel(
    const float* __restrict__ enc,
    const float* __restrict__ Wih0,
    const float* __restrict__ bih0,
    const float* __restrict__ bhh0)
{
    int g = threadIdx.x;                                   // gate 0..511
    float w[64];
#pragma unroll
    for (int e = 0; e < 64; e++) w[e] = Wih0[g * 80 + e];
    float bias = bih0[g] + bhh0[g];

    __shared__ __align__(16) float4 xs[16];                // one enc row (64 f)
    int total = BB * NNODE;
    int per = (total + gridDim.x - 1) / gridDim.x;
    int r0 = blockIdx.x * per;
    int r1 = min(r0 + per, total);
    for (int r = r0; r < r1; r++) {
        __syncthreads();
        if (g < 16) xs[g] = ((const float4*)(enc + (size_t)r * 64))[g];
        __syncthreads();
        float acc = bias;
#pragma unroll
        for (int e4 = 0; e4 < 16; e4++) {
            float4 x = xs[e4];
            acc += w[e4*4+0]*x.x + w[e4*4+1]*x.y + w[e4*4+2]*x.z + w[e4*4+3]*x.w;
        }
        g_genc[(size_t)r * G4 + g] = acc;
    }
}

// ---------------- kernel 3: software-pipelined recurrence -------------------
__global__ __launch_bounds__(256, 1) void rec_kernel(
    const float* __restrict__ s0,    // (1,16)
    const float* __restrict__ h0,    // (2,16)
    const float* __restrict__ c0,    // (2,128)
    const float* __restrict__ Wih0,  // (512,80)
    const float* __restrict__ Whh0,  // (512,16)
    const float* __restrict__ Whr0,  // (16,128)
    const float* __restrict__ Wih1,  // (512,16)
    const float* __restrict__ Whh1,  // (512,16)
    const float* __restrict__ bih1,  // (512)
    const float* __restrict__ bhh1,  // (512)
    const float* __restrict__ Whr1,  // (16,128)
    float* __restrict__ out)         // (B,FUT,N,O)
{
    const int b   = blockIdx.x;
    const int tid = threadIdx.x;
    const int k   = tid & 127;
    const bool isL0 = tid < 128;

    __shared__ __align__(16) float s_last[16];   // h2 carry (seeded with s0)
    __shared__ __align__(16) float s_h1[16];
    __shared__ __align__(16) float s_h2[16];     // h2 (seeded with h0[1])
    __shared__ __align__(16) float s_nm[2][16];  // ping-pong by node parity
    __shared__ __align__(16) float s_hf0[128];
    __shared__ __align__(16) float s_hf1[128];

    // packed weights (per gate q, 16 ull = 32 floats), gates i,f,o pre-scaled 0.5:
    //  L0: [0:8) = W_ih0 loop cols (mult. last / nm), [8:16) = W_hh0 (mult. h1)
    //  L1: [0:8) = W_ih1 (mult. h1),                  [8:16) = W_hh1 (mult. h2)
    ull w2[4][16];
    ull wpr2[16];                    // 32-elem projection segment (k<64 only)
    float bias[4];
    float c_reg;

    {
        const int po = k >> 2, ps = k & 3;      // proj output / segment (k<64)
        if (isL0) {
#pragma unroll
            for (int q = 0; q < 4; q++) {
                const float sc = (q == 2) ? 1.0f : 0.5f;
                int g = q * 128 + k;
#pragma unroll
                for (int j = 0; j < 8; j++) {
                    w2[q][j]     = pk(sc * Wih0[g * 80 + 64 + 2*j], sc * Wih0[g * 80 + 64 + 2*j + 1]);
                    w2[q][8 + j] = pk(sc * Whh0[g * 16 + 2*j],      sc * Whh0[g * 16 + 2*j + 1]);
                }
                bias[q] = 0.f;
            }
            c_reg = c0[k];
            if (k < 64) {
#pragma unroll
                for (int j = 0; j < 16; j++)
                    wpr2[j] = pk(Whr0[po * 128 + ps * 32 + 2*j],
                                 Whr0[po * 128 + ps * 32 + 2*j + 1]);
            }
        } else {
#pragma unroll
            for (int q = 0; q < 4; q++) {
                const float sc = (q == 2) ? 1.0f : 0.5f;
                int g = q * 128 + k;
#pragma unroll
                for (int j = 0; j < 8; j++) {
                    w2[q][j]     = pk(sc * Wih1[g * 16 + 2*j], sc * Wih1[g * 16 + 2*j + 1]);
                    w2[q][8 + j] = pk(sc * Whh1[g * 16 + 2*j], sc * Whh1[g * 16 + 2*j + 1]);
                }
                bias[q] = sc * (bih1[g] + bhh1[g]);
            }
            c_reg = c0[128 + k];
            if (k < 64) {
#pragma unroll
                for (int j = 0; j < 16; j++)
                    wpr2[j] = pk(Whr1[po * 128 + ps * 32 + 2*j],
                                 Whr1[po * 128 + ps * 32 + 2*j + 1]);
            }
        }
    }

    if (tid < 16) {
        s_last[tid]   = s0[tid];
        s_h1[tid]     = h0[tid];
        s_h2[tid]     = h0[16 + tid];
        s_nm[0][tid]  = g_nm[(size_t)b * NNODE * OO + tid];
    }
    __syncthreads();

    ull  partial2[4];                 // packed off-cycle gate partials
    float genc_c[4], genc_n[4], gnm[4];
    float nm_pref = 0.f;

    if (isL0) {
        size_t base = (size_t)b * NNODE * G4 + k;
#pragma unroll
        for (int q = 0; q < 4; q++) {
            const float sc = (q == 2) ? 1.0f : 0.5f;
            genc_c[q] = sc * g_genc[base + q * 128];
            genc_n[q] = sc * g_genc[base + G4 + q * 128];   // node 1
        }
        if (k < 16) nm_pref = g_nm[((size_t)b * NNODE + 1) * OO + k];
        // gnm(node0): W_loop(scaled) . nm
        {
            ull a[4];
#pragma unroll
            for (int q = 0; q < 4; q++) a[q] = pk(0.f, 0.f);
            const ulonglong2* nm4 = (const ulonglong2*)s_nm[0];
#pragma unroll
            for (int i = 0; i < 4; i++) {
                ulonglong2 xx = nm4[i];
#pragma unroll
                for (int q = 0; q < 4; q++) {
                    ffma2(a[q], w2[q][2*i],     xx.x);
                    ffma2(a[q], w2[q][2*i + 1], xx.y);
                }
            }
#pragma unroll
            for (int q = 0; q < 4; q++) gnm[q] = hsum(a[q]);
        }
        // partial0(t=0) = genc + gnm + Whh0@h1_0  (kept packed)
        {
#pragma unroll
            for (int q = 0; q < 4; q++) partial2[q] = pk(genc_c[q] + gnm[q], 0.f);
            const ulonglong2* h14 = (const ulonglong2*)s_h1;
#pragma unroll
            for (int i = 0; i < 4; i++) {
                ulonglong2 xx = h14[i];
#pragma unroll
                for (int q = 0; q < 4; q++) {
                    ffma2(partial2[q], w2[q][8 + 2*i], xx.x);
                    ffma2(partial2[q], w2[q][9 + 2*i], xx.y);
                }
            }
        }
    } else {
        // partial1(t=0) = bias + Whh1@h2_0  (kept packed)
#pragma unroll
        for (int q = 0; q < 4; q++) partial2[q] = pk(bias[q], 0.f);
        const ulonglong2* h24 = (const ulonglong2*)s_h2;
#pragma unroll
        for (int i = 0; i < 4; i++) {
            ulonglong2 xx = h24[i];
#pragma unroll
            for (int q = 0; q < 4; q++) {
                ffma2(partial2[q], w2[q][8 + 2*i], xx.x);
                ffma2(partial2[q], w2[q][9 + 2*i], xx.y);
            }
        }
        ARRIVE3();                    // publish initial state to L0 (pairs L0 t=0 SYNC3)
    }

    int n = 0, f = 0;
    const int po = k >> 2, ps = k & 3;

    for (int t = 0; t < TOT; t++) {
        if (isL0) {
            // ================= layer 0 =================
            SYNC3();                              // h2_{t-1} (s_last) ready
            ull acc0 = partial2[0], acc1 = partial2[1];
            ull acc2 = partial2[2], acc3 = partial2[3];
            const ulonglong2* x4 = (const ulonglong2*)s_last;
#pragma unroll
            for (int i = 0; i < 4; i++) {
                ulonglong2 xx = x4[i];
                ffma2(acc0, w2[0][2*i], xx.x);  ffma2(acc0, w2[0][2*i+1], xx.y);
                ffma2(acc1, w2[1][2*i], xx.x);  ffma2(acc1, w2[1][2*i+1], xx.y);
                ffma2(acc2, w2[2][2*i], xx.x);  ffma2(acc2, w2[2][2*i+1], xx.y);
                ffma2(acc3, w2[3][2*i], xx.x);  ffma2(acc3, w2[3][2*i+1], xx.y);
            }
            float ig = sigm_h(hsum(acc0));
            float fg = sigm_h(hsum(acc1));
            float gg = tanhapx(hsum(acc2));
            float og = sigm_h(hsum(acc3));
            c_reg = fmaf(fg, c_reg, ig * gg);
            s_hf0[k] = og * tanhapx(c_reg);
            BAR1();                               // hf0 visible in L0

            if (k < 64) {                         // proj h1: 4 threads/output
                const ulonglong2* hf4 = (const ulonglong2*)(s_hf0 + ps * 32);
                ull pa = pk(0.f, 0.f), pb = pk(0.f, 0.f);
#pragma unroll
                for (int i = 0; i < 4; i++) {
                    ulonglong2 xa = hf4[2*i], xb = hf4[2*i + 1];
                    ffma2(pa, wpr2[4*i + 0], xa.x);
                    ffma2(pa, wpr2[4*i + 1], xa.y);
                    ffma2(pb, wpr2[4*i + 2], xb.x);
                    ffma2(pb, wpr2[4*i + 3], xb.y);
                }
                float p = hsum(pa) + hsum(pb);
                p += __shfl_xor_sync(0xffffffffu, p, 2);
                p += __shfl_xor_sync(0xffffffffu, p, 1);
                if (ps == 0) s_h1[po] = p;
            }
            SYNC4();                              // release L1 + h1 visible to L0

            // ---- off-cycle prep for step t+1 ----
            int f1 = f + 1, n1 = n;
            if (f1 == FUT) { f1 = 0; n1 = n + 1; }
            if (n1 < NNODE) {
                if (f1 == 0) {                    // node boundary
                    if (k < 16) {
                        s_nm[n1 & 1][k] = nm_pref;
                        int np = (n1 + 1 < NNODE) ? n1 + 1 : n1;
                        nm_pref = g_nm[((size_t)b * NNODE + np) * OO + k];
                    }
                    BAR1();
                    ull a[4];
#pragma unroll
                    for (int q = 0; q < 4; q++) a[q] = pk(0.f, 0.f);
                    const ulonglong2* nm4 = (const ulonglong2*)s_nm[n1 & 1];
#pragma unroll
                    for (int i = 0; i < 4; i++) {
                        ulonglong2 xx = nm4[i];
#pragma unroll
                        for (int q = 0; q < 4; q++) {
                            ffma2(a[q], w2[q][2*i],     xx.x);
                            ffma2(a[q], w2[q][2*i + 1], xx.y);
                        }
                    }
#pragma unroll
                    for (int q = 0; q < 4; q++) gnm[q] = hsum(a[q]);
#pragma unroll
                    for (int q = 0; q < 4; q++) genc_c[q] = genc_n[q];
                    int np = (n1 + 1 < NNODE) ? n1 + 1 : n1;
                    size_t base = ((size_t)b * NNODE + np) * G4 + k;
#pragma unroll
                    for (int q = 0; q < 4; q++) {
                        const float sc = (q == 2) ? 1.0f : 0.5f;
                        genc_n[q] = sc * g_genc[base + q * 128];
                    }
                }
#pragma unroll
                for (int q = 0; q < 4; q++) partial2[q] = pk(genc_c[q] + gnm[q], 0.f);
                const ulonglong2* h14 = (const ulonglong2*)s_h1;
#pragma unroll
                for (int i = 0; i < 4; i++) {
                    ulonglong2 xx = h14[i];
#pragma unroll
                    for (int q = 0; q < 4; q++) {
                        ffma2(partial2[q], w2[q][8 + 2*i], xx.x);
                        ffma2(partial2[q], w2[q][9 + 2*i], xx.y);
                    }
                }
            }
            f = f1; n = n1;
        } else {
            // ================= layer 1 =================
            SYNC4();                              // h1_t ready
            ull acc0 = partial2[0], acc1 = partial2[1];
            ull acc2 = partial2[2], acc3 = partial2[3];
            const ulonglong2* h14 = (const ulonglong2*)s_h1;
#pragma unroll
            for (int i = 0; i < 4; i++) {
                ulonglong2 xx = h14[i];
                ffma2(acc0, w2[0][2*i], xx.x);  ffma2(acc0, w2[0][2*i+1], xx.y);
                ffma2(acc1, w2[1][2*i], xx.x);  ffma2(acc1, w2[1][2*i+1], xx.y);
                ffma2(acc2, w2[2][2*i], xx.x);  ffma2(acc2, w2[2][2*i+1], xx.y);
                ffma2(acc3, w2[3][2*i], xx.x);  ffma2(acc3, w2[3][2*i+1], xx.y);
            }
            float ig = sigm_h(hsum(acc0));
            float fg = sigm_h(hsum(acc1));
            float gg = tanhapx(hsum(acc2));
            float og = sigm_h(hsum(acc3));
            c_reg = fmaf(fg, c_reg, ig * gg);
            s_hf1[k] = og * tanhapx(c_reg);
            BAR2();                               // hf1 visible in L1

            float p = 0.f;
            if (k < 64) {                         // proj h2
                const ulonglong2* hf4 = (const ulonglong2*)(s_hf1 + ps * 32);
                ull pa = pk(0.f, 0.f), pb = pk(0.f, 0.f);
#pragma unroll
                for (int i = 0; i < 4; i++) {
                    ulonglong2 xa = hf4[2*i], xb = hf4[2*i + 1];
                    ffma2(pa, wpr2[4*i + 0], xa.x);
                    ffma2(pa, wpr2[4*i + 1], xa.y);
                    ffma2(pb, wpr2[4*i + 2], xb.x);
                    ffma2(pb, wpr2[4*i + 3], xb.y);
                }
                p = hsum(pa) + hsum(pb);
                p += __shfl_xor_sync(0xffffffffu, p, 2);
                p += __shfl_xor_sync(0xffffffffu, p, 1);
                if (ps == 0) { s_h2[po] = p; s_last[po] = p; }
            }

            if (t < TOT - 1) {
                SYNC3();                          // release L0 + h2 visible to L1

                if (k < 64 && ps == 0)            // output (off-cycle)
                    out[(((size_t)b * FUT + f) * NNODE + n) * OO + po]
                        = p + s_nm[n & 1][po];

                // ---- off-cycle prep: partial1 for t+1 (packed) ----
#pragma unroll
                for (int q = 0; q < 4; q++) partial2[q] = pk(bias[q], 0.f);
                const ulonglong2* h24 = (const ulonglong2*)s_h2;
#pragma unroll
                for (int i = 0; i < 4; i++) {
                    ulonglong2 xx = h24[i];
#pragma unroll
                    for (int q = 0; q < 4; q++) {
                        ffma2(partial2[q], w2[q][8 + 2*i], xx.x);
                        ffma2(partial2[q], w2[q][9 + 2*i], xx.y);
                    }
                }
            } else {
                if (k < 64 && ps == 0)            // final output, no sync needed
                    out[(((size_t)b * FUT + f) * NNODE + n) * OO + po]
                        = p + s_nm[n & 1][po];
            }
            if (++f == FUT) { f = 0; ++n; }
        }
    }
}

// ---------------- launch ----------------------------------------------------
extern "C" void kernel_launch(void* const* d_in, const int* in_sizes, int n_in,
                              void* d_out, int out_size)
{
    const float* enc  = (const float*)d_in[0];   // (64,1,1000,64)
    const float* mean = (const float*)d_in[1];   // (64,12,1000,16)
    const float* s    = (const float*)d_in[2];   // (1,16)
    const float* h0   = (const float*)d_in[3];   // (2,16)
    const float* c0   = (const float*)d_in[4];   // (2,128)
    const float* Wih0 = (const float*)d_in[5];   // (512,80)
    const float* Whh0 = (const float*)d_in[6];   // (512,16)
    const float* bih0 = (const float*)d_in[7];   // (512)
    const float* bhh0 = (const float*)d_in[8];   // (512)
    const float* Whr0 = (const float*)d_in[9];   // (16,128)
    const float* Wih1 = (const float*)d_in[10];  // (512,16)
    const float* Whh1 = (const float*)d_in[11];  // (512,16)
    const float* bih1 = (const float*)d_in[12];  // (512)
    const float* bhh1 = (const float*)d_in[13];  // (512)
    const float* Whr1 = (const float*)d_in[14];  // (16,128)
    float* out = (float*)d_out;                  // (64,12,1000,16) fp32

    nm_kernel<<<(BB * NNODE * 4 + 255) / 256, 256>>>(mean);
    genc_kernel<<<148, 512>>>(enc, Wih0, bih0, bhh0);
    rec_kernel<<<BB, 256>>>(s, h0, c0, Wih0, Whh0, Whr0,
                            Wih1, Whh1, bih1, bhh1, Whr1, out);
}